// round 13
// baseline (speedup 1.0000x reference)
#include <cuda_runtime.h>

// ResidualEmbedding: per-frame Burg LPC (order 12) residual, sign-modulated embed.
// R13: R10 core (4 frames/warp, 8 lanes/frame, 20 samples/lane) with a[] DISTRIBUTED
// across the frame's 8 lanes (lane lh owns a[lh] and a[lh+8]):
//  - update: 2 SHFL + 2 predicated FMA per iter, off the critical chain
//  - frees 11 registers -> launch_bounds(256,5) -> 5 blocks/SM (40 warps)
//  - a[] gathered via 13 SHFLs after the loop (f/b registers dead by then)
//  - last iteration skips the f/b/den update (only r_11 -> a needed)

namespace {

constexpr int FRAME   = 160;
constexpr int ORDER   = 12;
constexpr int NFRAMES = 4096 * 15;       // 61440
constexpr int WPB     = 8;               // warps per block (32 frames/block)
constexpr int THREADS = WPB * 32;
constexpr int ROW     = 176;             // 12 halo + 160 + 4 pad (floats)
constexpr unsigned FULL = 0xffffffffu;

__device__ __forceinline__ float grp_sum(float v) {
#pragma unroll
    for (int o = 4; o > 0; o >>= 1) v += __shfl_xor_sync(FULL, v, o);
    return v;
}

__device__ __forceinline__ float fast_rcp(float x) {
    float r; asm("rcp.approx.f32 %0, %1;" : "=f"(r) : "f"(x)); return r;
}

__global__ __launch_bounds__(THREADS, 5) void burg_residual_kernel(
    const int*   __restrict__ bits,
    const float* __restrict__ pcm,
    const float* __restrict__ alpha_p,
    float*       __restrict__ out)
{
    const int warp   = threadIdx.x >> 5;
    const int lane   = threadIdx.x & 31;
    const int frame0 = (blockIdx.x * WPB + warp) * 4;   // exact grid
    const int sub    = lane >> 3;        // frame within warp
    const int lh     = lane & 7;         // lane within frame
    const int jb     = 20 * lh;          // my contiguous j-range start
    const int base   = lane & ~7;        // first lane of my frame group

    __shared__ float Xs[WPB][4][ROW];
    float* __restrict__ P = &Xs[warp][sub][0];          // sample j at P[12+j]

    // ---- Vectorized load: 20 contiguous samples (5 x LDG.128) ----
    const float* __restrict__ src = pcm + (long long)(frame0 + sub) * FRAME + jb;
    float x[20];
    {
        const float4* s4 = (const float4*)src;
#pragma unroll
        for (int k = 0; k < 5; ++k) {
            const float4 v = s4[k];
            x[4*k] = v.x; x[4*k+1] = v.y; x[4*k+2] = v.z; x[4*k+3] = v.w;
        }
    }
    {   // stash raw samples + zero halo (P[0..11]) for FIR
        float4* Pd = (float4*)(P + 12 + jb);
#pragma unroll
        for (int k = 0; k < 5; ++k)
            Pd[k] = make_float4(x[4*k], x[4*k+1], x[4*k+2], x[4*k+3]);
        if (lh < 3) ((float4*)P)[lh] = make_float4(0.f, 0.f, 0.f, 0.f);
    }

    // ---- Window (np.hanning: 0.5 - 0.5*cos(2*pi*j/159)) ----
    float b[20];
#pragma unroll
    for (int c = 0; c < 20; ++c) {
        const float w = 0.5f - 0.5f * __cosf((6.283185307179586f / 159.0f) * (float)(jb + c));
        b[c] = x[c] * w;
    }

    // ---- Init: f[j]=xw[j+1] (valid j<=158); j=159 entries = 0 ----
    float f[20];
#pragma unroll
    for (int c = 0; c < 19; ++c) f[c] = b[c + 1];
    {
        const float nxt = __shfl_sync(FULL, b[0], lane + 1);
        f[19] = (lh == 7) ? 0.f : nxt;
    }
    if (lh == 7) b[19] = 0.f;

    float den;
    {
        float p0 = 0.f, p1 = 0.f;
#pragma unroll
        for (int c = 0; c < 20; c += 2) {
            p0 = fmaf(f[c],   f[c],   fmaf(b[c],   b[c],   p0));
            p1 = fmaf(f[c+1], f[c+1], fmaf(b[c+1], b[c+1], p1));
        }
        den = grp_sum(p0 + p1);
    }
    float inv_den = fast_rcp(den);

    // ---- Distributed a: lane lh owns a[lh] (lo) and a[lh+8] (hi) ----
    float a_lo = (lh == 0) ? 1.f : 0.f;
    float a_hi = 0.f;

    // ---- Burg recursion. Invariant at iter i entry: f[j]=b[j]=0 for j>=159-i ----
#pragma unroll
    for (int i = 0; i < ORDER; ++i) {
        float p0 = 0.f, p1 = 0.f;
#pragma unroll
        for (int c = 0; c < 20; c += 2) {
            p0 = fmaf(f[c],   b[c],   p0);
            p1 = fmaf(f[c+1], b[c+1], p1);
        }
        const float s = grp_sum(p0 + p1);
        const float r = -2.f * s * inv_den;      // inv_den ready since last iter

        if (i < ORDER - 1) {                     // last iter: only a-update needed
            // in-place: f <- f + r*b ; b <- b + r*f_old
#pragma unroll
            for (int c = 0; c < 20; ++c) {
                const float fo = f[c];
                f[c] = fmaf(r, b[c], f[c]);
                b[c] = fmaf(r, fo,   b[c]);
            }

            // den_{i+1} = (1-r^2)*den - b_new[158-i]^2 - f_new[0]^2
            const int jl = 158 - i, Ll = jl / 20, cl = jl % 20;   // compile-time
            const float nf19 = __shfl_sync(FULL, f[0], lane + 1);
            const float t0   = __shfl_sync(FULL, f[0], base);
            const float ub   = __shfl_sync(FULL, b[cl], base | Ll);
            den = (1.f - r * r) * den - ub * ub - t0 * t0;
            inv_den = fast_rcp(den);             // off-chain: overlaps next dot

            // f' = shift-by-1(f); b': zero newly-invalid element
#pragma unroll
            for (int c = 0; c < 19; ++c) f[c] = f[c + 1];
            f[19] = (lh == 7) ? 0.f : nf19;
            if (lh == Ll) b[cl] = 0.f;
        }

        // distributed a-update: a[k] += r * a_old[i+1-k] for k <= i+1.
        // For both owned k (lh and lh+8), source index m = i+1-k lives in the
        // SAME lane s = base | ((i+1-lh)&7): lo if m<8, hi if m>=8.
        {
            const int m0 = (i + 1) - lh;
            const int sl = base | (m0 & 7);
            const float v_lo = __shfl_sync(FULL, a_lo, sl);
            const float v_hi = __shfl_sync(FULL, a_hi, sl);
            if (lh <= i + 1)     a_lo = fmaf(r, (m0 >= 8) ? v_hi : v_lo, a_lo);
            if (lh + 8 <= i + 1) a_hi = fmaf(r, v_lo, a_hi);
        }
    }

    // ---- Gather full a[0..12] into every lane (f/b registers dead now) ----
    float a[ORDER + 1];
#pragma unroll
    for (int k = 0; k < 8; ++k)  a[k] = __shfl_sync(FULL, a_lo, base | k);
#pragma unroll
    for (int k = 8; k <= ORDER; ++k) a[k] = __shfl_sync(FULL, a_hi, base | (k - 8));

    // ---- FIR on raw samples: 32-float register window (8 x LDS.128) ----
    __syncwarp();   // halo/sample STS visible across the group
    float xf[32];   // X[jb-12 .. jb+19]
    {
        const float4* W = (const float4*)(P + jb);   // = &P[12 + jb - 12]
#pragma unroll
        for (int k = 0; k < 8; ++k) {
            const float4 v = W[k];
            xf[4*k] = v.x; xf[4*k+1] = v.y; xf[4*k+2] = v.z; xf[4*k+3] = v.w;
        }
    }

    const float sgn  = 2.f * (float)__ldg(&bits[frame0 + sub]) - 1.f;
    const float coef = __ldg(alpha_p) * sgn;

    float o[20];
#pragma unroll
    for (int c = 0; c < 20; ++c) {
        float acc = a[0] * xf[12 + c];
#pragma unroll
        for (int k = 1; k <= ORDER; ++k)
            acc = fmaf(a[k], xf[12 + c - k], acc);
        o[c] = fmaf(coef, acc, xf[12 + c]);
    }

    // ---- Vectorized store (5 x STG.128) ----
    float* __restrict__ dst = out + (long long)(frame0 + sub) * FRAME + jb;
    float4* d4 = (float4*)dst;
#pragma unroll
    for (int k = 0; k < 5; ++k)
        d4[k] = make_float4(o[4*k], o[4*k+1], o[4*k+2], o[4*k+3]);
}

} // namespace

extern "C" void kernel_launch(void* const* d_in, const int* in_sizes, int n_in,
                              void* d_out, int out_size)
{
    const int*   bits  = (const int*)  d_in[0];
    const float* pcm   = (const float*)d_in[1];
    const float* alpha = (const float*)d_in[2];
    float*       out   = (float*)d_out;

    const int grid = NFRAMES / (WPB * 4);   // 1920 blocks
    burg_residual_kernel<<<grid, THREADS>>>(bits, pcm, alpha, out);
}

// round 14
// speedup vs baseline: 1.0023x; 1.0023x over previous
#include <cuda_runtime.h>

// ResidualEmbedding: per-frame Burg LPC (order 12) residual, sign-modulated embed.
// R14: R10 loop skeleton + R13 distributed-a (lane lh owns a[lh], a[lh+8]) +
// R11 sliding-window FIR (16-float window, 4 outputs/step, peak ~38 live regs).
// launch_bounds(256,5): 51-reg budget -> 5 blocks/SM (40 warps).
// R13 lesson: the 48-reg spill was the 32-float FIR window, not the loop.

namespace {

constexpr int FRAME   = 160;
constexpr int ORDER   = 12;
constexpr int NFRAMES = 4096 * 15;       // 61440
constexpr int WPB     = 8;               // warps per block (32 frames/block)
constexpr int THREADS = WPB * 32;
constexpr int ROW     = 176;             // 12 halo + 160 + 4 pad (floats)
constexpr unsigned FULL = 0xffffffffu;

__device__ __forceinline__ float grp_sum(float v) {
#pragma unroll
    for (int o = 4; o > 0; o >>= 1) v += __shfl_xor_sync(FULL, v, o);
    return v;
}

__device__ __forceinline__ float fast_rcp(float x) {
    float r; asm("rcp.approx.f32 %0, %1;" : "=f"(r) : "f"(x)); return r;
}

__global__ __launch_bounds__(THREADS, 5) void burg_residual_kernel(
    const int*   __restrict__ bits,
    const float* __restrict__ pcm,
    const float* __restrict__ alpha_p,
    float*       __restrict__ out)
{
    const int warp   = threadIdx.x >> 5;
    const int lane   = threadIdx.x & 31;
    const int frame0 = (blockIdx.x * WPB + warp) * 4;   // exact grid
    const int sub    = lane >> 3;        // frame within warp
    const int lh     = lane & 7;         // lane within frame

    __shared__ float Xs[WPB][4][ROW];
    float* __restrict__ P = &Xs[warp][sub][0];          // sample j at P[12+j]

    // ---- Vectorized load: 20 contiguous samples (5 x LDG.128) ----
    const float* __restrict__ src = pcm + (long long)(frame0 + sub) * FRAME + 20 * lh;
    float b[20];                          // raw -> windowed -> Burg b
    {
        const float4* s4 = (const float4*)src;
        float4*       Pd = (float4*)(P + 12 + 20 * lh);
#pragma unroll
        for (int k = 0; k < 5; ++k) {
            const float4 v = s4[k];
            Pd[k] = v;                                   // raw samples for FIR
            b[4*k] = v.x; b[4*k+1] = v.y; b[4*k+2] = v.z; b[4*k+3] = v.w;
        }
        if (lh < 3) ((float4*)P)[lh] = make_float4(0.f, 0.f, 0.f, 0.f);
    }

    // ---- Window (np.hanning: 0.5 - 0.5*cos(2*pi*j/159)) ----
#pragma unroll
    for (int c = 0; c < 20; ++c) {
        const float w =
            0.5f - 0.5f * __cosf((6.283185307179586f / 159.0f) * (float)(20 * lh + c));
        b[c] *= w;
    }

    // ---- Init: f[j]=xw[j+1] (valid j<=158); j=159 entries = 0 ----
    float f[20];
#pragma unroll
    for (int c = 0; c < 19; ++c) f[c] = b[c + 1];
    {
        const float nxt = __shfl_sync(FULL, b[0], lane + 1);
        f[19] = (lh == 7) ? 0.f : nxt;
    }
    if (lh == 7) b[19] = 0.f;

    float den;
    {
        float p0 = 0.f, p1 = 0.f;
#pragma unroll
        for (int c = 0; c < 20; c += 2) {
            p0 = fmaf(f[c],   f[c],   fmaf(b[c],   b[c],   p0));
            p1 = fmaf(f[c+1], f[c+1], fmaf(b[c+1], b[c+1], p1));
        }
        den = grp_sum(p0 + p1);
    }
    float inv_den = fast_rcp(den);

    // ---- Distributed a: lane lh owns a[lh] (lo) and a[lh+8] (hi) ----
    float a_lo = (lh == 0) ? 1.f : 0.f;
    float a_hi = 0.f;

    // ---- Burg recursion. Invariant at iter i entry: f[j]=b[j]=0 for j>=159-i ----
#pragma unroll
    for (int i = 0; i < ORDER; ++i) {
        float p0 = 0.f, p1 = 0.f;
#pragma unroll
        for (int c = 0; c < 20; c += 2) {
            p0 = fmaf(f[c],   b[c],   p0);
            p1 = fmaf(f[c+1], b[c+1], p1);
        }
        const float s = grp_sum(p0 + p1);
        const float r = -2.f * s * inv_den;      // inv_den ready since last iter

        if (i < ORDER - 1) {                     // last iter: only a-update needed
            // in-place: f <- f + r*b ; b <- b + r*f_old
#pragma unroll
            for (int c = 0; c < 20; ++c) {
                const float fo = f[c];
                f[c] = fmaf(r, b[c], f[c]);
                b[c] = fmaf(r, fo,   b[c]);
            }

            // den_{i+1} = (1-r^2)*den - b_new[158-i]^2 - f_new[0]^2
            const int jl = 158 - i, Ll = jl / 20, cl = jl % 20;   // compile-time
            const float nf19 = __shfl_sync(FULL, f[0], lane + 1);
            const float t0   = __shfl_sync(FULL, f[0], lane & ~7);
            const float ub   = __shfl_sync(FULL, b[cl], (lane & ~7) | Ll);
            den = (1.f - r * r) * den - ub * ub - t0 * t0;
            inv_den = fast_rcp(den);             // off-chain: overlaps next dot

            // f' = shift-by-1(f); b': zero newly-invalid element
#pragma unroll
            for (int c = 0; c < 19; ++c) f[c] = f[c + 1];
            f[19] = (lh == 7) ? 0.f : nf19;
            if (lh == Ll) b[cl] = 0.f;
        }

        // distributed a-update: a[k] += r*a_old[i+1-k], k<=i+1. Both owned k
        // source from the same lane sl = base|((i+1-lh)&7): lo if i+1-k<8 else hi.
        {
            const int m0 = (i + 1) - lh;
            const int sl = (lane & ~7) | (m0 & 7);
            const float v_lo = __shfl_sync(FULL, a_lo, sl);
            const float v_hi = __shfl_sync(FULL, a_hi, sl);
            if (lh <= i + 1)     a_lo = fmaf(r, (m0 >= 8) ? v_hi : v_lo, a_lo);
            if (lh + 8 <= i + 1) a_hi = fmaf(r, v_lo, a_hi);
        }
    }

    // ---- Gather full a[0..12] into every lane (f/b registers dead now) ----
    float a[ORDER + 1];
#pragma unroll
    for (int k = 0; k < 8; ++k)
        a[k] = __shfl_sync(FULL, a_lo, (lane & ~7) | k);
#pragma unroll
    for (int k = 8; k <= ORDER; ++k)
        a[k] = __shfl_sync(FULL, a_hi, (lane & ~7) | (k - 8));

    // ---- FIR: sliding 16-float window, 4 outputs per step (peak ~38 regs) ----
    __syncwarp();   // halo/sample STS visible across the group
    const float sgn  = 2.f * (float)__ldg(&bits[frame0 + sub]) - 1.f;
    const float coef = __ldg(alpha_p) * sgn;
    float* __restrict__ dst = out + (long long)(frame0 + sub) * FRAME + 20 * lh;

    float w[16];     // X[20lh-12+4g .. 20lh+3+4g]
    {
        const float4* W = (const float4*)(P + 20 * lh);   // = &P[12 + jb - 12]
#pragma unroll
        for (int k = 0; k < 4; ++k) {
            const float4 v = W[k];
            w[4*k]=v.x; w[4*k+1]=v.y; w[4*k+2]=v.z; w[4*k+3]=v.w;
        }
    }

#pragma unroll
    for (int g = 0; g < 5; ++g) {
        float4 o;
        float* op = &o.x;
#pragma unroll
        for (int t = 0; t < 4; ++t) {
            const float xc = w[12 + t];
            float acc = a[0] * xc;
#pragma unroll
            for (int k = 1; k <= ORDER; ++k)
                acc = fmaf(a[k], w[12 + t - k], acc);
            op[t] = fmaf(coef, acc, xc);
        }
        ((float4*)dst)[g] = o;
        if (g < 4) {   // slide window by 4
            const float4 v = ((const float4*)(P + 20 * lh))[4 + g];
#pragma unroll
            for (int k = 0; k < 12; ++k) w[k] = w[k + 4];
            w[12]=v.x; w[13]=v.y; w[14]=v.z; w[15]=v.w;
        }
    }
}

} // namespace

extern "C" void kernel_launch(void* const* d_in, const int* in_sizes, int n_in,
                              void* d_out, int out_size)
{
    const int*   bits  = (const int*)  d_in[0];
    const float* pcm   = (const float*)d_in[1];
    const float* alpha = (const float*)d_in[2];
    float*       out   = (float*)d_out;

    const int grid = NFRAMES / (WPB * 4);   // 1920 blocks
    burg_residual_kernel<<<grid, THREADS>>>(bits, pcm, alpha, out);
}

// round 15
// speedup vs baseline: 1.0520x; 1.0496x over previous
#include <cuda_runtime.h>

// ResidualEmbedding: per-frame Burg LPC (order 12) residual, sign-modulated embed.
// R15: 2 frames/warp, 16 lanes/frame, 10 samples/lane.
// Loop state: f[10]+b[10]+distributed a (1 reg, lane lh owns a[lh]) ~45 regs
// -> 5 blocks/SM spill-free (R13/R14 lesson: 20-sample loop can't fit 48 regs).
// Keeps: hoisted rcp, last-iter skip, zero-propagation invariant, sliding FIR.

namespace {

constexpr int FRAME   = 160;
constexpr int ORDER   = 12;
constexpr int NFRAMES = 4096 * 15;       // 61440
constexpr int WPB     = 8;               // warps per block (16 frames/block)
constexpr int THREADS = WPB * 32;
constexpr int ROW     = 176;             // 12 halo + 160 + 4 pad (floats)
constexpr unsigned FULL = 0xffffffffu;

// reduce over each 16-lane half independently (2 frames at once)
__device__ __forceinline__ float half_sum(float v) {
#pragma unroll
    for (int o = 8; o > 0; o >>= 1) v += __shfl_xor_sync(FULL, v, o);
    return v;
}

__device__ __forceinline__ float fast_rcp(float x) {
    float r; asm("rcp.approx.f32 %0, %1;" : "=f"(r) : "f"(x)); return r;
}

__global__ __launch_bounds__(THREADS, 5) void burg_residual_kernel(
    const int*   __restrict__ bits,
    const float* __restrict__ pcm,
    const float* __restrict__ alpha_p,
    float*       __restrict__ out)
{
    const int warp   = threadIdx.x >> 5;
    const int lane   = threadIdx.x & 31;
    const int frame0 = (blockIdx.x * WPB + warp) * 2;   // exact grid
    const int half   = lane >> 4;        // frame within warp
    const int lh     = lane & 15;        // lane within frame
    const int jb     = 10 * lh;          // my contiguous j-range start

    __shared__ float Xs[WPB][2][ROW];
    float* __restrict__ P = &Xs[warp][half][0];         // sample j at P[12+j]

    // ---- Load 10 contiguous samples (5 x LDG.64; 40B lane offset = 8B aligned) ----
    const float* __restrict__ src = pcm + (long long)(frame0 + half) * FRAME + jb;
    float b[10];                          // raw -> windowed -> Burg b
    {
        const float2* s2 = (const float2*)src;
        float2*       Pd = (float2*)(P + 12 + jb);
#pragma unroll
        for (int k = 0; k < 5; ++k) {
            const float2 v = s2[k];
            Pd[k] = v;                                   // raw samples for FIR
            b[2*k] = v.x; b[2*k+1] = v.y;
        }
        if (lh < 6) ((float2*)P)[lh] = make_float2(0.f, 0.f);   // P[0..11] = 0
    }

    // ---- Window (np.hanning: 0.5 - 0.5*cos(2*pi*j/159)) ----
#pragma unroll
    for (int c = 0; c < 10; ++c) {
        const float w =
            0.5f - 0.5f * __cosf((6.283185307179586f / 159.0f) * (float)(jb + c));
        b[c] *= w;
    }

    // ---- Init: f[j]=xw[j+1] (valid j<=158); j=159 entries = 0 ----
    float f[10];
#pragma unroll
    for (int c = 0; c < 9; ++c) f[c] = b[c + 1];
    {
        const float nxt = __shfl_sync(FULL, b[0], lane + 1);
        f[9] = (lh == 15) ? 0.f : nxt;
    }
    if (lh == 15) b[9] = 0.f;

    float den;
    {
        float p0 = 0.f, p1 = 0.f;
#pragma unroll
        for (int c = 0; c < 10; c += 2) {
            p0 = fmaf(f[c],   f[c],   fmaf(b[c],   b[c],   p0));
            p1 = fmaf(f[c+1], f[c+1], fmaf(b[c+1], b[c+1], p1));
        }
        den = half_sum(p0 + p1);
    }
    float inv_den = fast_rcp(den);

    // ---- Distributed a: lane lh owns a[lh] (lh <= 12; lanes 13-15 idle) ----
    float a_lo = (lh == 0) ? 1.f : 0.f;

    // ---- Burg recursion. Invariant at iter i entry: f[j]=b[j]=0 for j>=159-i ----
#pragma unroll
    for (int i = 0; i < ORDER; ++i) {
        float p0 = 0.f, p1 = 0.f;
#pragma unroll
        for (int c = 0; c < 10; c += 2) {
            p0 = fmaf(f[c],   b[c],   p0);
            p1 = fmaf(f[c+1], b[c+1], p1);
        }
        const float s = half_sum(p0 + p1);
        const float r = -2.f * s * inv_den;      // inv_den ready since last iter

        if (i < ORDER - 1) {                     // last iter: only a-update needed
            // in-place: f <- f + r*b ; b <- b + r*f_old
#pragma unroll
            for (int c = 0; c < 10; ++c) {
                const float fo = f[c];
                f[c] = fmaf(r, b[c], f[c]);
                b[c] = fmaf(r, fo,   b[c]);
            }

            // den_{i+1} = (1-r^2)*den - b_new[158-i]^2 - f_new[0]^2
            const int jl = 158 - i, Ll = jl / 10, cl = jl % 10;   // compile-time
            const float nf9 = __shfl_sync(FULL, f[0], lane + 1);  // for the shift
            const float t0  = __shfl_sync(FULL, f[0], lane & ~15);
            const float ub  = __shfl_sync(FULL, b[cl], (lane & ~15) | Ll);
            den = (1.f - r * r) * den - ub * ub - t0 * t0;
            inv_den = fast_rcp(den);             // off-chain: overlaps next dot

            // f' = shift-by-1(f); b': zero newly-invalid element
#pragma unroll
            for (int c = 0; c < 9; ++c) f[c] = f[c + 1];
            f[9] = (lh == 15) ? 0.f : nf9;
            if (lh == Ll) b[cl] = 0.f;
        }

        // distributed a-update: a[k] += r*a_old[i+1-k] for k <= i+1.
        // Source lane (i+1-lh) within my 16-lane half; 1 SHFL + 1 FMA.
        {
            const int sl = (lane & ~15) | (((i + 1) - lh) & 15);
            const float v = __shfl_sync(FULL, a_lo, sl);
            if (lh <= i + 1) a_lo = fmaf(r, v, a_lo);   // lh<=i+1<=12 excludes 13-15
        }
    }

    // ---- Gather full a[0..12] into every lane (f/b registers dead now) ----
    float a[ORDER + 1];
#pragma unroll
    for (int k = 0; k <= ORDER; ++k)
        a[k] = __shfl_sync(FULL, a_lo, (lane & ~15) | k);

    // ---- FIR: sliding 16-float window over X[jb-12 .. jb+9], direct stores ----
    __syncwarp();   // halo/sample STS visible across the group
    const float sgn  = 2.f * (float)__ldg(&bits[frame0 + half]) - 1.f;
    const float coef = __ldg(alpha_p) * sgn;
    float* __restrict__ dst = out + (long long)(frame0 + half) * FRAME + jb;

    float w[16];     // X[jb-12 .. jb+3]  (= P[jb .. jb+15])
    {
        const float2* W = (const float2*)(P + jb);
#pragma unroll
        for (int k = 0; k < 8; ++k) {
            const float2 v = W[k];
            w[2*k] = v.x; w[2*k+1] = v.y;
        }
    }

    // outputs 0-3, 4-7 (slide 4 between), then 8-9 (slide 2)
#pragma unroll
    for (int g = 0; g < 2; ++g) {
#pragma unroll
        for (int t = 0; t < 4; t += 2) {
            float2 o;
            {
                const float xc = w[12 + t];
                float acc = a[0] * xc;
#pragma unroll
                for (int k = 1; k <= ORDER; ++k)
                    acc = fmaf(a[k], w[12 + t - k], acc);
                o.x = fmaf(coef, acc, xc);
            }
            {
                const float xc = w[13 + t];
                float acc = a[0] * xc;
#pragma unroll
                for (int k = 1; k <= ORDER; ++k)
                    acc = fmaf(a[k], w[13 + t - k], acc);
                o.y = fmaf(coef, acc, xc);
            }
            ((float2*)dst)[(g * 4 + t) >> 1] = o;
        }
        // slide window by 4: bring in X[jb+4g+4 .. jb+4g+7]
        const float2* W = (const float2*)(P + jb);
        const float2 v0 = W[8 + 2 * g], v1 = W[9 + 2 * g];
#pragma unroll
        for (int k = 0; k < 12; ++k) w[k] = w[k + 4];
        w[12] = v0.x; w[13] = v0.y; w[14] = v1.x; w[15] = v1.y;
    }
    {   // outputs 8,9: current x at w[12],w[13] (window now X[jb-4 .. jb+11])
        float2 o;
        {
            const float xc = w[12];
            float acc = a[0] * xc;
#pragma unroll
            for (int k = 1; k <= ORDER; ++k)
                acc = fmaf(a[k], w[12 - k], acc);
            o.x = fmaf(coef, acc, xc);
        }
        {
            const float xc = w[13];
            float acc = a[0] * xc;
#pragma unroll
            for (int k = 1; k <= ORDER; ++k)
                acc = fmaf(a[k], w[13 - k], acc);
            o.y = fmaf(coef, acc, xc);
        }
        ((float2*)dst)[4] = o;
    }
}

} // namespace

extern "C" void kernel_launch(void* const* d_in, const int* in_sizes, int n_in,
                              void* d_out, int out_size)
{
    const int*   bits  = (const int*)  d_in[0];
    const float* pcm   = (const float*)d_in[1];
    const float* alpha = (const float*)d_in[2];
    float*       out   = (float*)d_out;

    const int grid = NFRAMES / (WPB * 2);   // 3840 blocks
    burg_residual_kernel<<<grid, THREADS>>>(bits, pcm, alpha, out);
}

// round 16
// speedup vs baseline: 1.1741x; 1.1160x over previous
#include <cuda_runtime.h>

// ResidualEmbedding: per-frame Burg LPC (order 12) residual, sign-modulated embed.
// R16: exact R10 kernel (best: 33.2us; 4 frames/warp, 8 lanes/frame, 20 samples/
// lane, a[] in registers, hoisted rcp) + two isolated, register-neutral cuts:
//  - last Burg iteration computes only r -> a-update (f/b/den update is dead work)
//  - bits/alpha prefetched before the loop (hides dependent LDG before stores)
// Lessons R8/R11/R13-R15: all occupancy-driven restructures lose; keep 64 regs.

namespace {

constexpr int FRAME   = 160;
constexpr int ORDER   = 12;
constexpr int NFRAMES = 4096 * 15;       // 61440
constexpr int WPB     = 8;               // warps per block (32 frames/block)
constexpr int THREADS = WPB * 32;
constexpr int ROW     = 176;             // 12 halo + 160 + 4 pad (floats, 16B-aligned)
constexpr unsigned FULL = 0xffffffffu;

// reduce over each 8-lane group independently (4 frames at once)
__device__ __forceinline__ float grp_sum(float v) {
#pragma unroll
    for (int o = 4; o > 0; o >>= 1) v += __shfl_xor_sync(FULL, v, o);
    return v;
}

__device__ __forceinline__ float fast_rcp(float x) {
    float r; asm("rcp.approx.f32 %0, %1;" : "=f"(r) : "f"(x)); return r;
}

__global__ __launch_bounds__(THREADS) void burg_residual_kernel(
    const int*   __restrict__ bits,
    const float* __restrict__ pcm,
    const float* __restrict__ alpha_p,
    float*       __restrict__ out)
{
    const int warp   = threadIdx.x >> 5;
    const int lane   = threadIdx.x & 31;
    const int frame0 = (blockIdx.x * WPB + warp) * 4;   // exact grid
    const int sub    = lane >> 3;        // frame within warp
    const int lh     = lane & 7;         // lane within frame
    const int jb     = 20 * lh;          // my contiguous j-range start

    __shared__ float Xs[WPB][4][ROW];
    float* __restrict__ P = &Xs[warp][sub][0];          // sample j at P[12+j]

    // ---- Prefetch scalars needed after the Burg loop ----
    const float sgn   = 2.f * (float)__ldg(&bits[frame0 + sub]) - 1.f;
    const float alpha = __ldg(alpha_p);

    // ---- Vectorized load: 20 contiguous samples (5 x LDG.128) ----
    const float* __restrict__ src = pcm + (long long)(frame0 + sub) * FRAME + jb;
    float x[20];
    {
        const float4* s4 = (const float4*)src;
#pragma unroll
        for (int k = 0; k < 5; ++k) {
            const float4 v = s4[k];
            x[4*k] = v.x; x[4*k+1] = v.y; x[4*k+2] = v.z; x[4*k+3] = v.w;
        }
    }
    {   // stash raw samples + zero halo (P[0..11]) for FIR
        float4* Pd = (float4*)(P + 12 + jb);
#pragma unroll
        for (int k = 0; k < 5; ++k)
            Pd[k] = make_float4(x[4*k], x[4*k+1], x[4*k+2], x[4*k+3]);
        if (lh < 3) ((float4*)P)[lh] = make_float4(0.f, 0.f, 0.f, 0.f);
    }

    // ---- Window (np.hanning: 0.5 - 0.5*cos(2*pi*j/159)) ----
    float xw[20];
#pragma unroll
    for (int c = 0; c < 20; ++c) {
        const float w = 0.5f - 0.5f * __cosf((6.283185307179586f / 159.0f) * (float)(jb + c));
        xw[c] = x[c] * w;
    }

    // ---- Init: b[j]=xw[j], f[j]=xw[j+1] (valid j<=158); j=159 entries = 0 ----
    float f[20], b[20];
#pragma unroll
    for (int c = 0; c < 20; ++c) b[c] = xw[c];
#pragma unroll
    for (int c = 0; c < 19; ++c) f[c] = xw[c + 1];
    {
        const float nxt = __shfl_sync(FULL, xw[0], lane + 1);
        f[19] = (lh == 7) ? 0.f : nxt;
    }
    if (lh == 7) b[19] = 0.f;

    float den;
    {
        float p0 = 0.f, p1 = 0.f;
#pragma unroll
        for (int c = 0; c < 20; c += 2) {
            p0 = fmaf(f[c],   f[c],   fmaf(b[c],   b[c],   p0));
            p1 = fmaf(f[c+1], f[c+1], fmaf(b[c+1], b[c+1], p1));
        }
        den = grp_sum(p0 + p1);
    }
    float inv_den = fast_rcp(den);

    float a[ORDER + 1];
    a[0] = 1.f;
#pragma unroll
    for (int k = 1; k <= ORDER; ++k) a[k] = 0.f;

    // ---- Burg recursion. Invariant at iter i entry: f[j]=b[j]=0 for j>=159-i ----
#pragma unroll
    for (int i = 0; i < ORDER; ++i) {
        float p0 = 0.f, p1 = 0.f;
#pragma unroll
        for (int c = 0; c < 20; c += 2) {
            p0 = fmaf(f[c],   b[c],   p0);
            p1 = fmaf(f[c+1], b[c+1], p1);
        }
        const float s = grp_sum(p0 + p1);
        const float r = -2.f * s * inv_den;      // inv_den ready since last iter

        if (i < ORDER - 1) {                     // last iter: only a-update needed
            // in-place: f <- f + r*b ; b <- b + r*f_old
#pragma unroll
            for (int c = 0; c < 20; ++c) {
                const float fo = f[c];
                f[c] = fmaf(r, b[c], f[c]);
                b[c] = fmaf(r, fo,   b[c]);
            }

            // den_{i+1} = (1-r^2)*den - b_new[158-i]^2 - f_new[0]^2
            const int jl = 158 - i, Ll = jl / 20, cl = jl % 20;   // compile-time
            const float nf19 = __shfl_sync(FULL, f[0], lane + 1); // for the shift
            const float t0   = __shfl_sync(FULL, f[0], lane & ~7);
            const float ub   = __shfl_sync(FULL, b[cl], (lane & ~7) | Ll);
            den = (1.f - r * r) * den - ub * ub - t0 * t0;
            inv_den = fast_rcp(den);             // off-chain: overlaps next dot

            // f' = shift-by-1(f); b': zero newly-invalid element
#pragma unroll
            for (int c = 0; c < 19; ++c) f[c] = f[c + 1];
            f[19] = (lh == 7) ? 0.f : nf19;
            if (lh == Ll) b[cl] = 0.f;
        }

        // a[:i+2] += r * reverse(a[:i+2])  -- pairwise in place
#pragma unroll
        for (int k = 0; 2 * k <= i + 1; ++k) {
            const int k2 = i + 1 - k;
            if (k2 == k) {
                a[k] = a[k] + r * a[k];
            } else {
                const float tmp = a[k];
                a[k]  = fmaf(r, a[k2], a[k]);
                a[k2] = fmaf(r, tmp,  a[k2]);
            }
        }
    }

    // ---- FIR on raw samples: 32-float register window (8 x LDS.128) ----
    __syncwarp();   // halo/sample STS visible across the group
    float xf[32];   // X[jb-12 .. jb+19]
    {
        const float4* W = (const float4*)(P + jb);   // = &P[12 + jb - 12]
#pragma unroll
        for (int k = 0; k < 8; ++k) {
            const float4 v = W[k];
            xf[4*k] = v.x; xf[4*k+1] = v.y; xf[4*k+2] = v.z; xf[4*k+3] = v.w;
        }
    }

    const float coef = alpha * sgn;

    float o[20];
#pragma unroll
    for (int c = 0; c < 20; ++c) {
        float acc = a[0] * xf[12 + c];
#pragma unroll
        for (int k = 1; k <= ORDER; ++k)
            acc = fmaf(a[k], xf[12 + c - k], acc);
        o[c] = fmaf(coef, acc, xf[12 + c]);
    }

    // ---- Vectorized store (5 x STG.128) ----
    float* __restrict__ dst = out + (long long)(frame0 + sub) * FRAME + jb;
    float4* d4 = (float4*)dst;
#pragma unroll
    for (int k = 0; k < 5; ++k)
        d4[k] = make_float4(o[4*k], o[4*k+1], o[4*k+2], o[4*k+3]);
}

} // namespace

extern "C" void kernel_launch(void* const* d_in, const int* in_sizes, int n_in,
                              void* d_out, int out_size)
{
    const int*   bits  = (const int*)  d_in[0];
    const float* pcm   = (const float*)d_in[1];
    const float* alpha = (const float*)d_in[2];
    float*       out   = (float*)d_out;

    const int grid = NFRAMES / (WPB * 4);   // 1920 blocks
    burg_residual_kernel<<<grid, THREADS>>>(bits, pcm, alpha, out);
}

// round 17
// speedup vs baseline: 1.2464x; 1.0616x over previous
#include <cuda_runtime.h>

// ResidualEmbedding: per-frame Burg LPC (order 12) residual, sign-modulated embed.
// FINAL (= R10, session best 33.2us): 4 frames/warp, 8 lanes/frame, 20 contiguous
// samples/lane.
//  - Burg recursion in compacted j-space: f<-f+r*b, b<-b+r*f_old, f'=shift1(f);
//    zero-propagation invariant on the invalid tail -> mask-free reductions.
//  - 3-step xor butterfly (4/2/1) reduces all 4 frames in one instruction stream.
//  - den reciprocal hoisted off the critical chain (rcp.approx overlaps next dot).
//  - a[] in registers, pairwise in-place update (compile-time indices, no spills).
//  - LDG.128/STS.128/LDS.128/STG.128 data movement; shared used only for the
//    12-sample FIR halo; 64 regs, 4 blocks/SM, spill-free.
// Rejected by measurement: f32x2 packing (R6), 2-chain ILP @128regs (R8),
// forced launch bounds (R9/R13/R14), shared-a (R11), window table (R12),
// 16-lane frames (R15), last-iter skip + prefetch (R16).

namespace {

constexpr int FRAME   = 160;
constexpr int ORDER   = 12;
constexpr int NFRAMES = 4096 * 15;       // 61440
constexpr int WPB     = 8;               // warps per block (32 frames/block)
constexpr int THREADS = WPB * 32;
constexpr int ROW     = 176;             // 12 halo + 160 + 4 pad (floats, 16B-aligned)
constexpr unsigned FULL = 0xffffffffu;

// reduce over each 8-lane group independently (4 frames at once)
__device__ __forceinline__ float grp_sum(float v) {
#pragma unroll
    for (int o = 4; o > 0; o >>= 1) v += __shfl_xor_sync(FULL, v, o);
    return v;
}

__device__ __forceinline__ float fast_rcp(float x) {
    float r; asm("rcp.approx.f32 %0, %1;" : "=f"(r) : "f"(x)); return r;
}

__global__ __launch_bounds__(THREADS) void burg_residual_kernel(
    const int*   __restrict__ bits,
    const float* __restrict__ pcm,
    const float* __restrict__ alpha_p,
    float*       __restrict__ out)
{
    const int warp   = threadIdx.x >> 5;
    const int lane   = threadIdx.x & 31;
    const int frame0 = (blockIdx.x * WPB + warp) * 4;   // exact grid
    const int sub    = lane >> 3;        // frame within warp
    const int lh     = lane & 7;         // lane within frame
    const int jb     = 20 * lh;          // my contiguous j-range start

    __shared__ float Xs[WPB][4][ROW];
    float* __restrict__ P = &Xs[warp][sub][0];          // sample j at P[12+j]

    // ---- Vectorized load: 20 contiguous samples (5 x LDG.128) ----
    const float* __restrict__ src = pcm + (long long)(frame0 + sub) * FRAME + jb;
    float x[20];
    {
        const float4* s4 = (const float4*)src;
#pragma unroll
        for (int k = 0; k < 5; ++k) {
            const float4 v = s4[k];
            x[4*k] = v.x; x[4*k+1] = v.y; x[4*k+2] = v.z; x[4*k+3] = v.w;
        }
    }
    {   // stash raw samples + zero halo (P[0..11]) for FIR
        float4* Pd = (float4*)(P + 12 + jb);
#pragma unroll
        for (int k = 0; k < 5; ++k)
            Pd[k] = make_float4(x[4*k], x[4*k+1], x[4*k+2], x[4*k+3]);
        if (lh < 3) ((float4*)P)[lh] = make_float4(0.f, 0.f, 0.f, 0.f);
    }

    // ---- Window (np.hanning: 0.5 - 0.5*cos(2*pi*j/159)) ----
    float xw[20];
#pragma unroll
    for (int c = 0; c < 20; ++c) {
        const float w = 0.5f - 0.5f * __cosf((6.283185307179586f / 159.0f) * (float)(jb + c));
        xw[c] = x[c] * w;
    }

    // ---- Init: b[j]=xw[j], f[j]=xw[j+1] (valid j<=158); j=159 entries = 0 ----
    float f[20], b[20];
#pragma unroll
    for (int c = 0; c < 20; ++c) b[c] = xw[c];
#pragma unroll
    for (int c = 0; c < 19; ++c) f[c] = xw[c + 1];
    {
        const float nxt = __shfl_sync(FULL, xw[0], lane + 1);
        f[19] = (lh == 7) ? 0.f : nxt;
    }
    if (lh == 7) b[19] = 0.f;

    float den;
    {
        float p0 = 0.f, p1 = 0.f;
#pragma unroll
        for (int c = 0; c < 20; c += 2) {
            p0 = fmaf(f[c],   f[c],   fmaf(b[c],   b[c],   p0));
            p1 = fmaf(f[c+1], f[c+1], fmaf(b[c+1], b[c+1], p1));
        }
        den = grp_sum(p0 + p1);
    }
    float inv_den = fast_rcp(den);

    float a[ORDER + 1];
    a[0] = 1.f;
#pragma unroll
    for (int k = 1; k <= ORDER; ++k) a[k] = 0.f;

    // ---- Burg recursion. Invariant at iter i entry: f[j]=b[j]=0 for j>=159-i ----
#pragma unroll
    for (int i = 0; i < ORDER; ++i) {
        float p0 = 0.f, p1 = 0.f;
#pragma unroll
        for (int c = 0; c < 20; c += 2) {
            p0 = fmaf(f[c],   b[c],   p0);
            p1 = fmaf(f[c+1], b[c+1], p1);
        }
        const float s = grp_sum(p0 + p1);
        const float r = -2.f * s * inv_den;      // inv_den ready since last iter

        // in-place: f <- t = f + r*b ; b <- u = b + r*f_old
#pragma unroll
        for (int c = 0; c < 20; ++c) {
            const float fo = f[c];
            f[c] = fmaf(r, b[c], f[c]);
            b[c] = fmaf(r, fo,   b[c]);
        }

        // den_{i+1} = (1-r^2)*den - b_new[158-i]^2 - f_new[0]^2
        const int jl = 158 - i, Ll = jl / 20, cl = jl % 20;   // compile-time
        const float nf19 = __shfl_sync(FULL, f[0], lane + 1); // for the shift
        const float t0   = __shfl_sync(FULL, f[0], lane & ~7);
        const float ub   = __shfl_sync(FULL, b[cl], (lane & ~7) | Ll);
        den = (1.f - r * r) * den - ub * ub - t0 * t0;
        inv_den = fast_rcp(den);                 // off-chain: overlaps next dot

        // f' = shift-by-1(f); b': zero newly-invalid element
#pragma unroll
        for (int c = 0; c < 19; ++c) f[c] = f[c + 1];
        f[19] = (lh == 7) ? 0.f : nf19;
        if (lh == Ll) b[cl] = 0.f;

        // a[:i+2] += r * reverse(a[:i+2])  -- pairwise in place
#pragma unroll
        for (int k = 0; 2 * k <= i + 1; ++k) {
            const int k2 = i + 1 - k;
            if (k2 == k) {
                a[k] = a[k] + r * a[k];
            } else {
                const float tmp = a[k];
                a[k]  = fmaf(r, a[k2], a[k]);
                a[k2] = fmaf(r, tmp,  a[k2]);
            }
        }
    }

    // ---- FIR on raw samples: 32-float register window (8 x LDS.128) ----
    __syncwarp();   // halo/sample STS visible across the group
    float xf[32];   // X[jb-12 .. jb+19]
    {
        const float4* W = (const float4*)(P + jb);   // = &P[12 + jb - 12]
#pragma unroll
        for (int k = 0; k < 8; ++k) {
            const float4 v = W[k];
            xf[4*k] = v.x; xf[4*k+1] = v.y; xf[4*k+2] = v.z; xf[4*k+3] = v.w;
        }
    }

    const float sgn  = 2.f * (float)__ldg(&bits[frame0 + sub]) - 1.f;
    const float coef = __ldg(alpha_p) * sgn;

    float o[20];
#pragma unroll
    for (int c = 0; c < 20; ++c) {
        float acc = a[0] * xf[12 + c];
#pragma unroll
        for (int k = 1; k <= ORDER; ++k)
            acc = fmaf(a[k], xf[12 + c - k], acc);
        o[c] = fmaf(coef, acc, xf[12 + c]);
    }

    // ---- Vectorized store (5 x STG.128) ----
    float* __restrict__ dst = out + (long long)(frame0 + sub) * FRAME + jb;
    float4* d4 = (float4*)dst;
#pragma unroll
    for (int k = 0; k < 5; ++k)
        d4[k] = make_float4(o[4*k], o[4*k+1], o[4*k+2], o[4*k+3]);
}

} // namespace

extern "C" void kernel_launch(void* const* d_in, const int* in_sizes, int n_in,
                              void* d_out, int out_size)
{
    const int*   bits  = (const int*)  d_in[0];
    const float* pcm   = (const float*)d_in[1];
    const float* alpha = (const float*)d_in[2];
    float*       out   = (float*)d_out;

    const int grid = NFRAMES / (WPB * 4);   // 1920 blocks
    burg_residual_kernel<<<grid, THREADS>>>(bits, pcm, alpha, out);
}